// round 14
// baseline (speedup 1.0000x reference)
#include <cuda_runtime.h>
#include <cuda_fp16.h>
#include <cstdint>

// ---------------- problem constants ----------------
#define NCOLS 8192
#define BLK   256
#define NBLK  16

// ---------------- tile config ----------------
#define BM 128      // output rows per CTA (half block)
#define BN 256      // output cols per CTA (8 warps x 32)
#define KC 16       // K chunk
#define NCHUNK 16   // 256/16
#define NSTAGE 3    // per-warp cp.async pipeline depth

// ---------------- SMEM layout (per CTA) ----------------
// A: W half-block fp16: 128 rows x (256 fp16 = 512B + 16B pad) = 528B/row
// X: per-warp private stages: 16 rows x (32 fp32 = 128B + 16B pad) = 144B/row
#define A_ROW 528
#define X_ROW 144
#define OFF_X (128 * A_ROW)                  // 67584
#define X_STAGE (KC * X_ROW)                 // 2304
#define W_XBYTES (NSTAGE * X_STAGE)          // 6912 per warp
#define SMEM_TOTAL (OFF_X + 8 * W_XBYTES)    // 122880
// C staging (epilogue) reuses A region: 128 rows x (128 fp32 + pad) = 528B/row
#define C_ROW 528

// fp16 copy of W, produced once per launch by conv_w kernel (2 MB)
__device__ __half g_Wh[NBLK * BLK * BLK];

// ---------------- helpers ----------------
__device__ __forceinline__ uint32_t smem_u32(const void* p) {
    uint32_t a;
    asm("{ .reg .u64 t; cvta.to.shared.u64 t, %1; cvt.u32.u64 %0, t; }" : "=r"(a) : "l"(p));
    return a;
}

__device__ __forceinline__ uint32_t cvt_f16x2(float x0, float x1) {
    uint32_t r;
    asm("cvt.rn.f16x2.f32 %0, %1, %2;" : "=r"(r) : "f"(x1), "f"(x0));
    return r;
}

__device__ __forceinline__ void cp16(uint32_t saddr, const void* g) {
    asm volatile("cp.async.cg.shared.global [%0], [%1], 16;" :: "r"(saddr), "l"(g));
}
__device__ __forceinline__ void cp_commit() {
    asm volatile("cp.async.commit_group;");
}
template <int N>
__device__ __forceinline__ void cp_wait() {
    asm volatile("cp.async.wait_group %0;" :: "n"(N));
}

__device__ __forceinline__ void ldm_x4(uint32_t (&r)[4], uint32_t addr) {
    asm volatile("ldmatrix.sync.aligned.m8n8.x4.shared.b16 {%0,%1,%2,%3}, [%4];"
                 : "=r"(r[0]), "=r"(r[1]), "=r"(r[2]), "=r"(r[3]) : "r"(addr));
}

__device__ __forceinline__ void mma_f16(float (&d)[4], const uint32_t (&a)[4],
                                        const uint32_t b0, const uint32_t b1) {
    asm volatile(
        "mma.sync.aligned.m16n8k16.row.col.f32.f16.f16.f32 "
        "{%0,%1,%2,%3}, {%4,%5,%6,%7}, {%8,%9}, {%0,%1,%2,%3};"
        : "+f"(d[0]), "+f"(d[1]), "+f"(d[2]), "+f"(d[3])
        : "r"(a[0]), "r"(a[1]), "r"(a[2]), "r"(a[3]), "r"(b0), "r"(b1));
}

// ---------------- W fp32 -> fp16 pre-pass ----------------
__global__ void conv_w(const float* __restrict__ W) {
    const int i = blockIdx.x * blockDim.x + threadIdx.x;
    const float2 v = ((const float2*)W)[i];
    *(uint32_t*)&g_Wh[2 * i] = cvt_f16x2(v.x, v.y);
}

// ---------------- main kernel: 256 threads, warp-autonomous pipelines ----------------
__global__ void __launch_bounds__(256, 1)
blk_gemm(const float* __restrict__ X,   // [4096, 8192]
         float* __restrict__ out)       // [4096, 8192]
{
    extern __shared__ char smem[];
    const uint32_t sb = smem_u32(smem);
    const int tid  = threadIdx.x;
    const int lane = tid & 31;
    const int w    = tid >> 5;     // 0..7 : warp owns cols w*32..w*32+31

    const int cta = blockIdx.x;
    const int nt  = cta & 31;              // N tile (256 cols)
    const int mt  = (cta >> 5) & 1;        // M half of block
    const int b   = cta >> 6;              // diag block

    // warp-private X stage base
    const uint32_t xw = sb + OFF_X + w * W_XBYTES;

    // per-warp cp.async mapping: 16 rows x 8 float4 = 128 copies, 4/lane
    const int xr = lane >> 3;           // base row 0..3 (+4j)
    const int xc = lane & 7;            // float4 col 0..7
    const float* Xw = X + (size_t)(b * BLK) * NCOLS + nt * BN + w * 32;

    // ---- issue first 2 stages of this warp's X slice ----
    #pragma unroll
    for (int s = 0; s < NSTAGE - 1; s++) {
        const float* Xs = Xw + (size_t)(s * KC) * NCOLS;
        const uint32_t st = xw + s * X_STAGE;
        #pragma unroll
        for (int j = 0; j < 4; j++)
            cp16(st + (xr + 4 * j) * X_ROW + xc * 16,
                 Xs + (size_t)(xr + 4 * j) * NCOLS + xc * 4);
        cp_commit();
    }

    // ---- prologue: copy W half-block (fp16, pre-converted) into SMEM ----
    {
        const uint4* src = (const uint4*)(g_Wh + (size_t)b * (BLK * BLK) +
                                          (size_t)mt * BM * BLK);   // 4096 uint4
        #pragma unroll 8
        for (int i = 0; i < 16; i++) {
            const int idx = tid + 256 * i;
            const int row = idx >> 5;          // 32 uint4 per row
            const int c16 = idx & 31;
            *(uint4*)(smem + row * A_ROW + c16 * 16) = src[idx];
        }
    }

    float acc[8][4][4];
    #pragma unroll
    for (int mi = 0; mi < 8; mi++)
        #pragma unroll
        for (int nj = 0; nj < 4; nj++)
            #pragma unroll
            for (int q = 0; q < 4; q++) acc[mi][nj][q] = 0.f;

    // B fragment coordinates (within warp's 32-col slice)
    const int k0 = (lane & 3) * 2;        // 0,2,4,6
    const int nb = (lane >> 2);           // 0..7

    __syncthreads();   // A tile ready (the ONLY CTA barrier before epilogue)

    // ---- main loop: NO CTA barriers; each warp self-paced ----
    for (int c = 0; c < NCHUNK; c++) {
        cp_wait<1>();       // this warp's stage c arrived
        __syncwarp();       // cross-lane visibility within warp

        // issue this warp's stage c+2 into slot (c+2)%3 (warp-private slot)
        if (c + 2 < NCHUNK) {
            const int s = c + 2;
            const float* Xs = Xw + (size_t)(s * KC) * NCOLS;
            const uint32_t st = xw + (s % NSTAGE) * X_STAGE;
            #pragma unroll
            for (int j = 0; j < 4; j++)
                cp16(st + (xr + 4 * j) * X_ROW + xc * 16,
                     Xs + (size_t)(xr + 4 * j) * NCOLS + xc * 4);
        }
        cp_commit();   // always commit (keeps wait<1> arithmetic valid)

        const uint32_t xst = xw + (c % NSTAGE) * X_STAGE;

        // A fragments: rows mi*16 + (lane&15), k bytes c*32 + (lane>>4)*16
        const uint32_t a_off =
            (uint32_t)((lane & 15) * A_ROW + c * 32 + (lane >> 4) * 16);
        uint32_t Ah[8][4];
        #pragma unroll
        for (int mi = 0; mi < 8; mi++)
            ldm_x4(Ah[mi], sb + a_off + mi * 16 * A_ROW);

        // B fragments from warp-private fp32 stage (conflict-free LDS.32) + cvt
        uint32_t B0[4], B1[4];
        #pragma unroll
        for (int nj = 0; nj < 4; nj++) {
            const int col = nj * 8 + nb;
            const char* p = smem + (xst - sb) + k0 * X_ROW + col * 4;
            float v0 = *(const float*)(p);
            float v1 = *(const float*)(p + X_ROW);
            float v2 = *(const float*)(p + 8 * X_ROW);
            float v3 = *(const float*)(p + 9 * X_ROW);
            B0[nj] = cvt_f16x2(v0, v1);
            B1[nj] = cvt_f16x2(v2, v3);
        }

        #pragma unroll
        for (int mi = 0; mi < 8; mi++)
            #pragma unroll
            for (int nj = 0; nj < 4; nj++)
                mma_f16(acc[mi][nj], Ah[mi], B0[nj], B1[nj]);
    }

    // ---- epilogue: 2-phase transpose through SMEM (reuse A region) ----
    float* const obase = out + (size_t)(b * BLK + mt * BM) * NCOLS + nt * BN;
    #pragma unroll
    for (int p = 0; p < 2; p++) {
        __syncthreads();   // phase p: region free (main loop / previous copy done)
        if ((w >> 2) == p) {
            const int lw = w & 3;                       // 0..3 within phase
            const int cr = lane >> 2;                   // +mi*16, +8 for v1
            const int cc = lw * 32 + (lane & 3) * 2;    // +nj*8
            #pragma unroll
            for (int mi = 0; mi < 8; mi++)
                #pragma unroll
                for (int nj = 0; nj < 4; nj++) {
                    float2 v0; v0.x = acc[mi][nj][0]; v0.y = acc[mi][nj][1];
                    float2 v1; v1.x = acc[mi][nj][2]; v1.y = acc[mi][nj][3];
                    char* base = smem + (cr + mi * 16) * C_ROW + (cc + nj * 8) * 4;
                    *(float2*)(base) = v0;
                    *(float2*)(base + 8 * C_ROW) = v1;
                }
        }
        __syncthreads();
        // cooperative coalesced write-out of this 128x128 half
        float* ob = obase + p * 128;
        #pragma unroll 8
        for (int i = 0; i < 16; i++) {
            const int idx  = tid + 256 * i;     // 4096 float4
            const int row  = idx >> 5;
            const int col4 = idx & 31;
            float4 v = *(float4*)(smem + row * C_ROW + col4 * 16);
            *(float4*)(ob + (size_t)row * NCOLS + col4 * 4) = v;
        }
    }
}

// ---------------- launch ----------------
extern "C" void kernel_launch(void* const* d_in, const int* in_sizes, int n_in,
                              void* d_out, int out_size) {
    const float* X = (const float*)d_in[0];   // inp [4096, 8192]
    const float* W = (const float*)d_in[1];   // W   [16, 256, 256]
    float* out = (float*)d_out;

    conv_w<<<(NBLK * BLK * BLK / 2) / 256, 256>>>(W);

    cudaFuncSetAttribute(blk_gemm, cudaFuncAttributeMaxDynamicSharedMemorySize, SMEM_TOTAL);
    dim3 grid(NBLK * 2 * (NCOLS / BN));   // 16 * 2 * 32 = 1024
    blk_gemm<<<grid, 256, SMEM_TOTAL>>>(X, out);
}

// round 15
// speedup vs baseline: 1.0625x; 1.0625x over previous
#include <cuda_runtime.h>
#include <cuda_fp16.h>
#include <cstdint>

// ---------------- problem constants ----------------
#define NCOLS 8192
#define BLK   256
#define NBLK  16

// ---------------- tile config ----------------
#define BM 128      // output rows per CTA (half block)
#define BN 256      // output cols per CTA (16 warps x 16)
#define KC 16       // K chunk
#define NCHUNK 16   // 256/16
#define NSTAGE 4    // per-warp cp.async pipeline depth

// ---------------- SMEM layout (per CTA) ----------------
// A: W half-block fp16: 128 rows x (256 fp16 = 512B + 16B pad) = 528B/row
// X: per-warp private stages: 16 rows x (16 fp32 = 64B + 16B pad) = 80B/row
#define A_ROW 528
#define X_ROW 80
#define OFF_X (128 * A_ROW)                   // 67584
#define X_STAGE (KC * X_ROW)                  // 1280
#define W_XBYTES (NSTAGE * X_STAGE)           // 5120 per warp
#define SMEM_TOTAL (OFF_X + 16 * W_XBYTES)    // 149504
// C staging (epilogue) reuses A region: 128 rows x (128 fp32 + pad) = 528B/row
#define C_ROW 528

// fp16 copy of W, produced once per launch by conv_w kernel (2 MB)
__device__ __half g_Wh[NBLK * BLK * BLK];

// ---------------- helpers ----------------
__device__ __forceinline__ uint32_t smem_u32(const void* p) {
    uint32_t a;
    asm("{ .reg .u64 t; cvta.to.shared.u64 t, %1; cvt.u32.u64 %0, t; }" : "=r"(a) : "l"(p));
    return a;
}

__device__ __forceinline__ uint32_t cvt_f16x2(float x0, float x1) {
    uint32_t r;
    asm("cvt.rn.f16x2.f32 %0, %1, %2;" : "=r"(r) : "f"(x1), "f"(x0));
    return r;
}

__device__ __forceinline__ void cp16(uint32_t saddr, const void* g) {
    asm volatile("cp.async.cg.shared.global [%0], [%1], 16;" :: "r"(saddr), "l"(g));
}
__device__ __forceinline__ void cp_commit() {
    asm volatile("cp.async.commit_group;");
}
template <int N>
__device__ __forceinline__ void cp_wait() {
    asm volatile("cp.async.wait_group %0;" :: "n"(N));
}

__device__ __forceinline__ void ldm_x4(uint32_t (&r)[4], uint32_t addr) {
    asm volatile("ldmatrix.sync.aligned.m8n8.x4.shared.b16 {%0,%1,%2,%3}, [%4];"
                 : "=r"(r[0]), "=r"(r[1]), "=r"(r[2]), "=r"(r[3]) : "r"(addr));
}

__device__ __forceinline__ void mma_f16(float (&d)[4], const uint32_t (&a)[4],
                                        const uint32_t b0, const uint32_t b1) {
    asm volatile(
        "mma.sync.aligned.m16n8k16.row.col.f32.f16.f16.f32 "
        "{%0,%1,%2,%3}, {%4,%5,%6,%7}, {%8,%9}, {%0,%1,%2,%3};"
        : "+f"(d[0]), "+f"(d[1]), "+f"(d[2]), "+f"(d[3])
        : "r"(a[0]), "r"(a[1]), "r"(a[2]), "r"(a[3]), "r"(b0), "r"(b1));
}

// ---------------- W fp32 -> fp16 pre-pass ----------------
__global__ void conv_w(const float* __restrict__ W) {
    const int i = blockIdx.x * blockDim.x + threadIdx.x;
    const float2 v = ((const float2*)W)[i];
    *(uint32_t*)&g_Wh[2 * i] = cvt_f16x2(v.x, v.y);
}

// ---------------- main kernel: 512 threads, 16 autonomous warp pipelines ----------------
__global__ void __launch_bounds__(512, 1)
blk_gemm(const float* __restrict__ X,   // [4096, 8192]
         float* __restrict__ out)       // [4096, 8192]
{
    extern __shared__ char smem[];
    const uint32_t sb = smem_u32(smem);
    const int tid  = threadIdx.x;
    const int lane = tid & 31;
    const int w    = tid >> 5;     // 0..15 : warp owns cols w*16..w*16+15

    const int cta = blockIdx.x;
    const int nt  = cta & 31;              // N tile (256 cols)
    const int mt  = (cta >> 5) & 1;        // M half of block
    const int b   = cta >> 6;              // diag block

    // warp-private X stage base
    const uint32_t xw = sb + OFF_X + w * W_XBYTES;

    // per-warp cp.async mapping: 16 rows x 4 float4 = 64 copies, 2/lane
    const int xr = lane >> 2;           // base row 0..7 (+8j)
    const int xc = lane & 3;            // float4 col 0..3
    const float* Xw = X + (size_t)(b * BLK) * NCOLS + nt * BN + w * 16;

    // ---- issue first 3 stages of this warp's X slice ----
    #pragma unroll
    for (int s = 0; s < NSTAGE - 1; s++) {
        const float* Xs = Xw + (size_t)(s * KC) * NCOLS;
        const uint32_t st = xw + s * X_STAGE;
        #pragma unroll
        for (int j = 0; j < 2; j++)
            cp16(st + (xr + 8 * j) * X_ROW + xc * 16,
                 Xs + (size_t)(xr + 8 * j) * NCOLS + xc * 4);
        cp_commit();
    }

    // ---- prologue: copy W half-block (fp16, pre-converted) into SMEM ----
    {
        const uint4* src = (const uint4*)(g_Wh + (size_t)b * (BLK * BLK) +
                                          (size_t)mt * BM * BLK);   // 4096 uint4
        #pragma unroll 8
        for (int i = 0; i < 8; i++) {
            const int idx = tid + 512 * i;
            const int row = idx >> 5;          // 32 uint4 per row
            const int c16 = idx & 31;
            *(uint4*)(smem + row * A_ROW + c16 * 16) = src[idx];
        }
    }

    float acc[8][2][4];
    #pragma unroll
    for (int mi = 0; mi < 8; mi++)
        #pragma unroll
        for (int nj = 0; nj < 2; nj++)
            #pragma unroll
            for (int q = 0; q < 4; q++) acc[mi][nj][q] = 0.f;

    // B fragment coordinates (within warp's 16-col slice)
    const int k0 = (lane & 3) * 2;        // 0,2,4,6
    const int nb = (lane >> 2);           // 0..7

    __syncthreads();   // A tile ready (the ONLY CTA barrier before epilogue)

    // ---- main loop: NO CTA barriers; each warp self-paced ----
    for (int c = 0; c < NCHUNK; c++) {
        cp_wait<2>();       // this warp's stage c arrived
        __syncwarp();       // cross-lane visibility within warp

        // issue this warp's stage c+3 into slot (c+3)&3 (warp-private slot)
        if (c + 3 < NCHUNK) {
            const int s = c + 3;
            const float* Xs = Xw + (size_t)(s * KC) * NCOLS;
            const uint32_t st = xw + (s & 3) * X_STAGE;
            #pragma unroll
            for (int j = 0; j < 2; j++)
                cp16(st + (xr + 8 * j) * X_ROW + xc * 16,
                     Xs + (size_t)(xr + 8 * j) * NCOLS + xc * 4);
        }
        cp_commit();   // always commit (keeps wait<2> arithmetic valid)

        const uint32_t xst = xw + (c & 3) * X_STAGE;

        // B fragments from warp-private fp32 stage (conflict-free LDS.32) + cvt
        uint32_t B0[2], B1[2];
        #pragma unroll
        for (int nj = 0; nj < 2; nj++) {
            const int col = nj * 8 + nb;
            const char* p = smem + (xst - sb) + k0 * X_ROW + col * 4;
            float v0 = *(const float*)(p);
            float v1 = *(const float*)(p + X_ROW);
            float v2 = *(const float*)(p + 8 * X_ROW);
            float v3 = *(const float*)(p + 9 * X_ROW);
            B0[nj] = cvt_f16x2(v0, v1);
            B1[nj] = cvt_f16x2(v2, v3);
        }

        // A fragments + MMA in two mi-halves (limits live registers)
        const uint32_t a_off =
            (uint32_t)((lane & 15) * A_ROW + c * 32 + (lane >> 4) * 16);
        #pragma unroll
        for (int h = 0; h < 2; h++) {
            uint32_t Ah[4][4];
            #pragma unroll
            for (int mi = 0; mi < 4; mi++)
                ldm_x4(Ah[mi], sb + a_off + (h * 4 + mi) * 16 * A_ROW);
            #pragma unroll
            for (int mi = 0; mi < 4; mi++)
                #pragma unroll
                for (int nj = 0; nj < 2; nj++)
                    mma_f16(acc[h * 4 + mi][nj], Ah[mi], B0[nj], B1[nj]);
        }
    }

    // ---- epilogue: 2-phase transpose through SMEM (reuse A region) ----
    float* const obase = out + (size_t)(b * BLK + mt * BM) * NCOLS + nt * BN;
    #pragma unroll
    for (int p = 0; p < 2; p++) {
        __syncthreads();   // phase p: region free (main loop / previous copy done)
        if ((w >> 3) == p) {
            const int lw = w & 7;                       // 0..7 within phase
            const int cr = lane >> 2;                   // +mi*16, +8 for v1
            const int cc = lw * 16 + (lane & 3) * 2;    // +nj*8
            #pragma unroll
            for (int mi = 0; mi < 8; mi++)
                #pragma unroll
                for (int nj = 0; nj < 2; nj++) {
                    float2 v0; v0.x = acc[mi][nj][0]; v0.y = acc[mi][nj][1];
                    float2 v1; v1.x = acc[mi][nj][2]; v1.y = acc[mi][nj][3];
                    char* base = smem + (cr + mi * 16) * C_ROW + (cc + nj * 8) * 4;
                    *(float2*)(base) = v0;
                    *(float2*)(base + 8 * C_ROW) = v1;
                }
        }
        __syncthreads();
        // cooperative coalesced write-out of this 128x128 half
        float* ob = obase + p * 128;
        #pragma unroll 8
        for (int i = 0; i < 8; i++) {
            const int idx  = tid + 512 * i;     // 4096 float4
            const int row  = idx >> 5;
            const int col4 = idx & 31;
            float4 v = *(float4*)(smem + row * C_ROW + col4 * 16);
            *(float4*)(ob + (size_t)row * NCOLS + col4 * 4) = v;
        }
    }
}

// ---------------- launch ----------------
extern "C" void kernel_launch(void* const* d_in, const int* in_sizes, int n_in,
                              void* d_out, int out_size) {
    const float* X = (const float*)d_in[0];   // inp [4096, 8192]
    const float* W = (const float*)d_in[1];   // W   [16, 256, 256]
    float* out = (float*)d_out;

    conv_w<<<(NBLK * BLK * BLK / 2) / 256, 256>>>(W);

    cudaFuncSetAttribute(blk_gemm, cudaFuncAttributeMaxDynamicSharedMemorySize, SMEM_TOTAL);
    dim3 grid(NBLK * 2 * (NCOLS / BN));   // 16 * 2 * 32 = 1024
    blk_gemm<<<grid, 512, SMEM_TOTAL>>>(X, out);
}

// round 16
// speedup vs baseline: 1.1117x; 1.0463x over previous
#include <cuda_runtime.h>
#include <cuda_fp16.h>
#include <cstdint>

// ---------------- problem constants ----------------
#define NCOLS 8192
#define BLK   256
#define NBLK  16

// ---------------- tile config ----------------
#define BM 128      // output rows per CTA (half block)
#define BN 256      // output cols per CTA (8 slices x 32)
#define KC 16       // K chunk
#define NCHUNK 16   // 256/16
#define NSTAGE 4    // cp.async ring depth per slice

// ---------------- SMEM layout (per CTA) ----------------
// A: W half-block fp16: 128 rows x (256 fp16 = 512B + 16B pad) = 528B/row
// X: 8 shared slices, each: NSTAGE x (16 rows x (32 fp32 = 128B + 16B pad) = 144B)
#define A_ROW 528
#define X_ROW 144
#define OFF_X (128 * A_ROW)                   // 67584
#define X_STAGE (KC * X_ROW)                  // 2304
#define SL_BYTES (NSTAGE * X_STAGE)           // 9216 per slice
#define SMEM_TOTAL (OFF_X + 8 * SL_BYTES)     // 141312
// C staging (epilogue) reuses A region: 128 rows x (128 fp32 + pad) = 528B/row
#define C_ROW 528

// fp16 copy of W, produced once per launch by conv_w kernel (2 MB)
__device__ __half g_Wh[NBLK * BLK * BLK];

// ---------------- helpers ----------------
__device__ __forceinline__ uint32_t smem_u32(const void* p) {
    uint32_t a;
    asm("{ .reg .u64 t; cvta.to.shared.u64 t, %1; cvt.u32.u64 %0, t; }" : "=r"(a) : "l"(p));
    return a;
}

__device__ __forceinline__ uint32_t cvt_f16x2(float x0, float x1) {
    uint32_t r;
    asm("cvt.rn.f16x2.f32 %0, %1, %2;" : "=r"(r) : "f"(x1), "f"(x0));
    return r;
}

__device__ __forceinline__ void cp16(uint32_t saddr, const void* g) {
    asm volatile("cp.async.cg.shared.global [%0], [%1], 16;" :: "r"(saddr), "l"(g));
}
__device__ __forceinline__ void cp_commit() {
    asm volatile("cp.async.commit_group;");
}
template <int N>
__device__ __forceinline__ void cp_wait() {
    asm volatile("cp.async.wait_group %0;" :: "n"(N));
}

// pair-scoped named barrier (64 threads)
__device__ __forceinline__ void bar_pair(int id) {
    asm volatile("bar.sync %0, 64;" :: "r"(id) : "memory");
}

__device__ __forceinline__ void ldm_x4(uint32_t (&r)[4], uint32_t addr) {
    asm volatile("ldmatrix.sync.aligned.m8n8.x4.shared.b16 {%0,%1,%2,%3}, [%4];"
                 : "=r"(r[0]), "=r"(r[1]), "=r"(r[2]), "=r"(r[3]) : "r"(addr));
}

__device__ __forceinline__ void mma_f16(float (&d)[4], const uint32_t (&a)[4],
                                        const uint32_t b0, const uint32_t b1) {
    asm volatile(
        "mma.sync.aligned.m16n8k16.row.col.f32.f16.f16.f32 "
        "{%0,%1,%2,%3}, {%4,%5,%6,%7}, {%8,%9}, {%0,%1,%2,%3};"
        : "+f"(d[0]), "+f"(d[1]), "+f"(d[2]), "+f"(d[3])
        : "r"(a[0]), "r"(a[1]), "r"(a[2]), "r"(a[3]), "r"(b0), "r"(b1));
}

// ---------------- W fp32 -> fp16 pre-pass ----------------
__global__ void conv_w(const float* __restrict__ W) {
    const int i = blockIdx.x * blockDim.x + threadIdx.x;
    const float2 v = ((const float2*)W)[i];
    *(uint32_t*)&g_Wh[2 * i] = cvt_f16x2(v.x, v.y);
}

// ---------------- main kernel: 512 threads, 8 producer/consumer warp pairs ----------------
__global__ void __launch_bounds__(512, 1)
blk_gemm(const float* __restrict__ X,   // [4096, 8192]
         float* __restrict__ out)       // [4096, 8192]
{
    extern __shared__ char smem[];
    const uint32_t sb = smem_u32(smem);
    const int tid  = threadIdx.x;
    const int lane = tid & 31;
    const int w    = tid >> 5;     // 0..15
    const int wm   = w & 1;        // M half within pair (64 rows)
    const int wn   = w >> 1;       // slice 0..7 (32 cols each)

    const int cta = blockIdx.x;
    const int nt  = cta & 31;              // N tile (256 cols)
    const int mt  = (cta >> 5) & 1;        // M half of block
    const int b   = cta >> 6;              // diag block

    // shared slice base for this pair
    const uint32_t xsl = sb + OFF_X + wn * SL_BYTES;

    // producer cp.async mapping: 16 rows x 8 float4 = 128 copies, 4/lane
    const int xr = lane >> 3;           // base row 0..3 (+4j)
    const int xc = lane & 7;            // float4 col 0..7
    const float* Xw = X + (size_t)(b * BLK) * NCOLS + nt * BN + wn * 32;

    // ---- producer issues first 3 stages of the pair's X slice ----
    if (wm == 0) {
        #pragma unroll
        for (int s = 0; s < NSTAGE - 1; s++) {
            const float* Xs = Xw + (size_t)(s * KC) * NCOLS;
            const uint32_t st = xsl + s * X_STAGE;
            #pragma unroll
            for (int j = 0; j < 4; j++)
                cp16(st + (xr + 4 * j) * X_ROW + xc * 16,
                     Xs + (size_t)(xr + 4 * j) * NCOLS + xc * 4);
            cp_commit();
        }
    }

    // ---- prologue: copy W half-block (fp16, pre-converted) into SMEM ----
    {
        const uint4* src = (const uint4*)(g_Wh + (size_t)b * (BLK * BLK) +
                                          (size_t)mt * BM * BLK);   // 4096 uint4
        #pragma unroll 8
        for (int i = 0; i < 8; i++) {
            const int idx = tid + 512 * i;
            const int row = idx >> 5;          // 32 uint4 per row
            const int c16 = idx & 31;
            *(uint4*)(smem + row * A_ROW + c16 * 16) = src[idx];
        }
    }

    float acc[4][4][4];
    #pragma unroll
    for (int mi = 0; mi < 4; mi++)
        #pragma unroll
        for (int nj = 0; nj < 4; nj++)
            #pragma unroll
            for (int q = 0; q < 4; q++) acc[mi][nj][q] = 0.f;

    // B fragment coordinates (within pair's 32-col slice)
    const int k0 = (lane & 3) * 2;        // 0,2,4,6
    const int nb = (lane >> 2);           // 0..7
    const int barid = 1 + wn;             // named barrier 1..8 (0 = __syncthreads)

    __syncthreads();   // A tile ready (the ONLY CTA barrier before epilogue)

    // ---- main loop: pair-scoped sync only ----
    for (int c = 0; c < NCHUNK; c++) {
        if (wm == 0) { cp_wait<2>(); }     // producer: stage c landed
        bar_pair(barid);                   // pair sync + memory ordering

        // producer issues stage c+3 into slot (c+3)&3 (both consumers past
        // their reads of that slot — they were retired before this barrier)
        if (wm == 0) {
            if (c + 3 < NCHUNK) {
                const int s = c + 3;
                const float* Xs = Xw + (size_t)(s * KC) * NCOLS;
                const uint32_t st = xsl + (s & 3) * X_STAGE;
                #pragma unroll
                for (int j = 0; j < 4; j++)
                    cp16(st + (xr + 4 * j) * X_ROW + xc * 16,
                         Xs + (size_t)(xr + 4 * j) * NCOLS + xc * 4);
            }
            cp_commit();   // empty groups keep wait<2> arithmetic valid
        }

        const uint32_t xst = xsl + (c & 3) * X_STAGE;

        // A fragments: rows wm*64 + mi*16 + (lane&15), k bytes c*32
        const uint32_t a_off =
            (uint32_t)((wm * 64 + (lane & 15)) * A_ROW + c * 32 + (lane >> 4) * 16);
        uint32_t Ah[4][4];
        #pragma unroll
        for (int mi = 0; mi < 4; mi++)
            ldm_x4(Ah[mi], sb + a_off + mi * 16 * A_ROW);

        // B fragments from shared fp32 slice (conflict-free LDS.32) + cvt
        uint32_t B0[4], B1[4];
        #pragma unroll
        for (int nj = 0; nj < 4; nj++) {
            const int col = nj * 8 + nb;
            const char* p = smem + (xst - sb) + k0 * X_ROW + col * 4;
            float v0 = *(const float*)(p);
            float v1 = *(const float*)(p + X_ROW);
            float v2 = *(const float*)(p + 8 * X_ROW);
            float v3 = *(const float*)(p + 9 * X_ROW);
            B0[nj] = cvt_f16x2(v0, v1);
            B1[nj] = cvt_f16x2(v2, v3);
        }

        #pragma unroll
        for (int mi = 0; mi < 4; mi++)
            #pragma unroll
            for (int nj = 0; nj < 4; nj++)
                mma_f16(acc[mi][nj], Ah[mi], B0[nj], B1[nj]);
    }

    // ---- epilogue: 2-phase transpose through SMEM (reuse A region) ----
    float* const obase = out + (size_t)(b * BLK + mt * BM) * NCOLS + nt * BN;
    #pragma unroll
    for (int p = 0; p < 2; p++) {
        __syncthreads();   // phase p: region free (main loop / previous copy done)
        if ((wn >> 2) == p) {
            const int cr = wm * 64 + (lane >> 2);             // +mi*16, +8 for v1
            const int cc = (wn & 3) * 32 + (lane & 3) * 2;    // +nj*8
            #pragma unroll
            for (int mi = 0; mi < 4; mi++)
                #pragma unroll
                for (int nj = 0; nj < 4; nj++) {
                    float2 v0; v0.x = acc[mi][nj][0]; v0.y = acc[mi][nj][1];
                    float2 v1; v1.x = acc[mi][nj][2]; v1.y = acc[mi][nj][3];
                    char* base = smem + (cr + mi * 16) * C_ROW + (cc + nj * 8) * 4;
                    *(float2*)(base) = v0;
                    *(float2*)(base + 8 * C_ROW) = v1;
                }
        }
        __syncthreads();
        // cooperative coalesced write-out of this 128x128 half
        float* ob = obase + p * 128;
        #pragma unroll 8
        for (int i = 0; i < 8; i++) {
            const int idx  = tid + 512 * i;     // 4096 float4
            const int row  = idx >> 5;
            const int col4 = idx & 31;
            float4 v = *(float4*)(smem + row * C_ROW + col4 * 16);
            *(float4*)(ob + (size_t)row * NCOLS + col4 * 4) = v;
        }
    }
}

// ---------------- launch ----------------
extern "C" void kernel_launch(void* const* d_in, const int* in_sizes, int n_in,
                              void* d_out, int out_size) {
    const float* X = (const float*)d_in[0];   // inp [4096, 8192]
    const float* W = (const float*)d_in[1];   // W   [16, 256, 256]
    float* out = (float*)d_out;

    conv_w<<<(NBLK * BLK * BLK / 2) / 256, 256>>>(W);

    cudaFuncSetAttribute(blk_gemm, cudaFuncAttributeMaxDynamicSharedMemorySize, SMEM_TOTAL);
    dim3 grid(NBLK * 2 * (NCOLS / BN));   // 16 * 2 * 32 = 1024
    blk_gemm<<<grid, 512, SMEM_TOTAL>>>(X, out);
}